// round 14
// baseline (speedup 1.0000x reference)
#include <cuda_runtime.h>
#include <cuda_fp16.h>
#include <cstdint>

#define V_TOT 32000
#define F_DIM 256
#define D_DIM 1024
#define R_TOT 8192

// pass A tiling (S = X @ W^T, then exp -> P), k streamed in 4 slabs of 64
#define AM 128
#define AV 128
#define ASLAB 64
#define ANSLAB (F_DIM / ASLAB)   // 4
#define NVT (V_TOT / AV)         // 250 v-tiles per row group
// pass B tiling (H = P @ E): 64x256 tiles, KV=32, 4 stages, mbarrier pipeline
#define BM 64
#define BD 256
#define BKV 32
#define BSTAGE 4
#define BDEPTH 3
#define BNCH (V_TOT / BKV)       // 1000

// fused grid: 64 groups x (250 A + 8 B)
#define GRP_SZ 258
#define NCTAS (64 * GRP_SZ)      // 16512

// ---- passA smem (halves) ----
#define AXP 72
#define A_STAGE_H (2 * AM * AXP)                  // 18432 halves per stage
#define A_P_OFF   (2 * A_STAGE_H)                 // 36864
#define APSP 136
#define A_SMEM_BYTES ((A_P_OFF + AM * APSP) * 2)  // 108,544 B

// ---- passB smem ----
#define PP 40                                     // 32 k + 8 pad (halves)
#define EP 264                                    // 256 d + 8 pad (halves)
#define B_STAGE_H (BM * PP + BKV * EP)            // 11008 halves = 22016 B
#define B_P_OFF 0
#define B_E_OFF (BM * PP)
#define B_MBAR_OFF (BSTAGE * B_STAGE_H * 2)       // 88064
// union smem size (A is larger)
#define U_SMEM_BYTES A_SMEM_BYTES

#define SPIN_CAP 10000000

// ---------------- static device scratch ----------------
__device__ __half g_W16[(size_t)V_TOT * F_DIM];   // (v, f) fp16
__device__ __half g_E16[(size_t)V_TOT * D_DIM];   // (v, d) fp16
__device__ __half g_X16[(size_t)R_TOT * F_DIM];   // (r, f) fp16 (permuted)
__device__ __half g_P[(size_t)R_TOT * V_TOT];     // (r, v) fp16 unnormalized probs
__device__ float  g_rsum[R_TOT];                  // per-row sum of exp
__device__ volatile int g_wm[64];                 // per-row-group v-tile watermark

// ---------------- PTX helpers ----------------
__device__ __forceinline__ unsigned saddr(const void* p) {
    return (unsigned)__cvta_generic_to_shared(p);
}
__device__ __forceinline__ void ldsm4(unsigned& r0, unsigned& r1, unsigned& r2, unsigned& r3, unsigned a) {
    asm volatile("ldmatrix.sync.aligned.m8n8.x4.shared.b16 {%0,%1,%2,%3},[%4];"
                 : "=r"(r0), "=r"(r1), "=r"(r2), "=r"(r3) : "r"(a));
}
__device__ __forceinline__ void ldsm4t(unsigned& r0, unsigned& r1, unsigned& r2, unsigned& r3, unsigned a) {
    asm volatile("ldmatrix.sync.aligned.m8n8.x4.trans.shared.b16 {%0,%1,%2,%3},[%4];"
                 : "=r"(r0), "=r"(r1), "=r"(r2), "=r"(r3) : "r"(a));
}
__device__ __forceinline__ void mma16816(float* c, const unsigned* a, unsigned b0, unsigned b1) {
    asm volatile(
        "mma.sync.aligned.m16n8k16.row.col.f32.f16.f16.f32 "
        "{%0,%1,%2,%3},{%4,%5,%6,%7},{%8,%9},{%0,%1,%2,%3};"
        : "+f"(c[0]), "+f"(c[1]), "+f"(c[2]), "+f"(c[3])
        : "r"(a[0]), "r"(a[1]), "r"(a[2]), "r"(a[3]), "r"(b0), "r"(b1));
}
__device__ __forceinline__ void cp16(unsigned dst, const void* src) {
    asm volatile("cp.async.cg.shared.global [%0],[%1],16;" :: "r"(dst), "l"(src) : "memory");
}
#define CP_COMMIT() asm volatile("cp.async.commit_group;" ::: "memory")
template <int N> __device__ __forceinline__ void cp_wait() {
    asm volatile("cp.async.wait_group %0;" :: "n"(N) : "memory");
}

// mbarrier primitives
#define MBAR_INIT(a, n) \
    asm volatile("mbarrier.init.shared.b64 [%0], %1;" :: "r"(a), "r"(n) : "memory")
#define MBAR_ARRIVE(a) \
    asm volatile("mbarrier.arrive.shared.b64 _, [%0];" :: "r"(a) : "memory")
#define MBAR_WAIT(a, p) do {                                                            \
    asm volatile("{\n\t.reg .pred P1;\n\t"                                              \
        "W%=:\n\tmbarrier.try_wait.parity.acquire.cta.shared::cta.b64 P1, [%0], %1, 0x989680;\n\t" \
        "@P1 bra.uni D%=;\n\tbra.uni W%=;\n\tD%=:\n\t}"                                 \
        :: "r"((unsigned)(a)), "r"((unsigned)(p)) : "memory");                          \
} while (0)

// ---------------- prep kernels ----------------
__global__ void cvt_w(const float* __restrict__ W) {      // (f,v) f32 -> (v,f) f16
    __shared__ float t[32][33];
    int v0 = blockIdx.x * 32, f0 = blockIdx.y * 32;
    int tx = threadIdx.x, ty = threadIdx.y;  // (32,8)
#pragma unroll
    for (int k = 0; k < 32; k += 8)
        t[ty + k][tx] = W[(size_t)(f0 + ty + k) * V_TOT + v0 + tx];
    __syncthreads();
#pragma unroll
    for (int k = 0; k < 32; k += 8)
        g_W16[(size_t)(v0 + ty + k) * F_DIM + f0 + tx] = __float2half(t[tx][ty + k]);
}

__global__ void cvt_e(const float4* __restrict__ E) {     // (v,d) f32 -> (v,d) f16
    int i = blockIdx.x * blockDim.x + threadIdx.x;
    float4 v = E[i];
    __half2* dst = (__half2*)g_E16;
    dst[2 * (size_t)i]     = __floats2half2_rn(v.x, v.y);
    dst[2 * (size_t)i + 1] = __floats2half2_rn(v.z, v.w);
}

__global__ void cvt_x(const float* __restrict__ x) {      // (B,N,F,T) -> (r,f); zero rsum + wm
    __shared__ float sm[256][33];
    int bn = blockIdx.x;
    int b = bn >> 6, n = bn & 63;
    const float* src = x + ((size_t)b * 64 + n) * (F_DIM * 32);
    int tid = threadIdx.x;
#pragma unroll 4
    for (int i = tid; i < F_DIM * 32; i += 256) sm[i >> 5][i & 31] = src[i];
    __syncthreads();
#pragma unroll 4
    for (int t = 0; t < 32; ++t) {
        int r = b * 2048 + t * 64 + n;
        g_X16[(size_t)r * F_DIM + tid] = __float2half(sm[tid][t]);
    }
    if (tid < 32) g_rsum[b * 2048 + tid * 64 + n] = 0.f;
    if (bn == 0 && tid < 64) g_wm[tid] = 0;
}

// ---------------- fused kernel: interleaved passA + passB ----------------
__global__ void __launch_bounds__(256, 2)
fusedAB(const float* __restrict__ bias, float* __restrict__ out) {
    extern __shared__ __align__(16) __half smem[];
    const unsigned sb = saddr(smem);
    const int tid  = threadIdx.x;
    const int lane = tid & 31;
    const int wid  = tid >> 5;
    const int bid  = blockIdx.x;
    const int grp  = bid / GRP_SZ;   // row group: 128 rows, passA tile index
    const int rr   = bid % GRP_SZ;

    if (rr < NVT) {
        // ================= passA: row_tile=grp, v_tile=rr =================
        const int warp_m = wid >> 1;    // 0..3 (32 rows)
        const int warp_n = wid & 1;     // 0..1 (64 cols)
        const int row_base = grp * AM;
        const int v_base   = rr * AV;

        const __half* Xsrc = g_X16 + (size_t)row_base * F_DIM;
        const __half* Wsrc = g_W16 + (size_t)v_base * F_DIM;

        auto issue_slab = [&](int s) {
            const int st = s & 1;
            const unsigned xs = sb + (st * A_STAGE_H) * 2;
            const unsigned ws = xs + (AM * AXP) * 2;
            const int k0 = s * ASLAB;
#pragma unroll
            for (int i = 0; i < 4; ++i) {
                int idx = tid + i * 256;
                int r = idx >> 3, sg = idx & 7;
                cp16(xs + (r * AXP + sg * 8) * 2, Xsrc + (size_t)r * F_DIM + k0 + sg * 8);
            }
#pragma unroll
            for (int i = 0; i < 4; ++i) {
                int idx = tid + i * 256;
                int r = idx >> 3, sg = idx & 7;
                cp16(ws + (r * AXP + sg * 8) * 2, Wsrc + (size_t)r * F_DIM + k0 + sg * 8);
            }
            CP_COMMIT();
        };

        float acc[2][8][4];
#pragma unroll
        for (int a = 0; a < 2; a++)
#pragma unroll
            for (int b = 0; b < 8; b++)
#pragma unroll
                for (int c = 0; c < 4; c++) acc[a][b][c] = 0.f;

        issue_slab(0);

        const int m_base = warp_m * 32;
#pragma unroll
        for (int s = 0; s < ANSLAB; ++s) {
            cp_wait<0>();
            __syncthreads();
            if (s + 1 < ANSLAB) issue_slab(s + 1);

            const int st = s & 1;
            const unsigned xs = sb + (st * A_STAGE_H) * 2;
            const unsigned ws = xs + (AM * AXP) * 2;
#pragma unroll
            for (int ks = 0; ks < ASLAB / 16; ++ks) {
                unsigned a0[4], a1[4];
                ldsm4(a0[0], a0[1], a0[2], a0[3],
                      xs + ((m_base + (lane & 15)) * AXP + ks * 16 + ((lane >> 4) << 3)) * 2);
                ldsm4(a1[0], a1[1], a1[2], a1[3],
                      xs + ((m_base + 16 + (lane & 15)) * AXP + ks * 16 + ((lane >> 4) << 3)) * 2);
#pragma unroll
                for (int nb = 0; nb < 4; ++nb) {
                    unsigned b0, b1, b2, b3;
                    int wrow = warp_n * 64 + nb * 16 + ((lane >> 4) << 3) + (lane & 7);
                    int koff = ks * 16 + (((lane >> 3) & 1) << 3);
                    ldsm4(b0, b1, b2, b3, ws + (wrow * AXP + koff) * 2);
                    mma16816(acc[0][nb * 2],     a0, b0, b1);
                    mma16816(acc[0][nb * 2 + 1], a0, b2, b3);
                    mma16816(acc[1][nb * 2],     a1, b0, b1);
                    mma16816(acc[1][nb * 2 + 1], a1, b2, b3);
                }
            }
        }
        __syncthreads();

        // exp -> fp16 stage + rowsum partials
        float rs[4] = {0.f, 0.f, 0.f, 0.f};
#pragma unroll
        for (int mt = 0; mt < 2; ++mt) {
            int r0 = m_base + mt * 16 + (lane >> 2);
#pragma unroll
            for (int nt = 0; nt < 8; ++nt) {
                int c0 = warp_n * 64 + nt * 8 + (lane & 3) * 2;
                float bv0 = __ldg(bias + v_base + c0);
                float bv1 = __ldg(bias + v_base + c0 + 1);
                float e0 = __expf(acc[mt][nt][0] + bv0);
                float e1 = __expf(acc[mt][nt][1] + bv1);
                __half2 h01 = __floats2half2_rn(e0, e1);
                *(__half2*)(smem + A_P_OFF + r0 * APSP + c0) = h01;
                rs[mt * 2] += __low2float(h01) + __high2float(h01);
                float e2 = __expf(acc[mt][nt][2] + bv0);
                float e3 = __expf(acc[mt][nt][3] + bv1);
                __half2 h23 = __floats2half2_rn(e2, e3);
                *(__half2*)(smem + A_P_OFF + (r0 + 8) * APSP + c0) = h23;
                rs[mt * 2 + 1] += __low2float(h23) + __high2float(h23);
            }
        }
#pragma unroll
        for (int j = 0; j < 4; ++j) {
            rs[j] += __shfl_xor_sync(0xffffffffu, rs[j], 1);
            rs[j] += __shfl_xor_sync(0xffffffffu, rs[j], 2);
        }
        if ((lane & 3) == 0) {
#pragma unroll
            for (int j = 0; j < 4; ++j) {
                int row = m_base + (j >> 1) * 16 + (lane >> 2) + (j & 1) * 8;
                atomicAdd(&g_rsum[row_base + row], rs[j]);
            }
        }
        __syncthreads();

        // coalesced copy stage -> g_P
#pragma unroll
        for (int i = 0; i < 8; ++i) {
            int idx = tid + i * 256;
            int r = idx >> 4, s = idx & 15;
            *(uint4*)(g_P + (size_t)(row_base + r) * V_TOT + v_base + s * 8) =
                *(const uint4*)(smem + A_P_OFF + r * APSP + s * 8);
        }

        // publish watermark (ordered per row group)
        __threadfence();
        __syncthreads();
        if (tid == 0) {
            int it = 0;
            while (g_wm[grp] != rr && ++it < SPIN_CAP) ;
            g_wm[grp] = rr + 1;
        }
    } else {
        // ================= passB: rowB = grp*2 + q/4, d = q%4 =================
        const int q    = rr - NVT;             // 0..7
        const int warp_m = wid >> 2;           // 0..1 (32 rows)
        const int warp_n = wid & 3;            // 0..3 (64 cols)
        const int row_base = (grp * 2 + (q >> 2)) * BM;
        const int d_base   = (q & 3) * BD;

        const unsigned mbF = sb + B_MBAR_OFF;
        const unsigned mbE = sb + B_MBAR_OFF + 32;

        if (tid == 0) {
#pragma unroll
            for (int s = 0; s < BSTAGE; ++s) {
                MBAR_INIT(mbF + 8 * s, 256);
                MBAR_INIT(mbE + 8 * s, 256);
            }
        }
        __syncthreads();

        float hacc[2][8][4];
#pragma unroll
        for (int a = 0; a < 2; a++)
#pragma unroll
            for (int b = 0; b < 8; b++)
#pragma unroll
                for (int c = 0; c < 4; c++) hacc[a][b][c] = 0.f;

        int wm = 0;  // cached watermark (v-tiles done in this row group)
        auto wait_v = [&](int j) {            // need v-tile j>>2 complete
            int need = j >> 2;
            if (wm <= need) {
                int it = 0;
                while ((wm = g_wm[grp]) <= need && ++it < SPIN_CAP) ;
            }
        };

        auto issue_chunk = [&](int c) {
            const int st = c & (BSTAGE - 1);
            const unsigned ps = sb + (st * B_STAGE_H + B_P_OFF) * 2;
            const unsigned es = sb + (st * B_STAGE_H + B_E_OFF) * 2;
            const int v0 = c * BKV;
            {
                int r = tid >> 2, s = tid & 3;
                cp16(ps + (r * PP + s * 8) * 2, g_P + (size_t)(row_base + r) * V_TOT + v0 + s * 8);
            }
#pragma unroll
            for (int i = 0; i < 4; ++i) {
                int idx = tid + i * 256;
                int r = idx >> 5, s = idx & 31;
                cp16(es + (r * EP + s * 8) * 2, g_E16 + (size_t)(v0 + r) * D_DIM + d_base + s * 8);
            }
            CP_COMMIT();
        };

        // prologue: stages 0..2, publish full[0]
        wait_v(0); issue_chunk(0);
        wait_v(1); issue_chunk(1);
        wait_v(2); issue_chunk(2);
        cp_wait<2>();
        MBAR_ARRIVE(mbF + 0);

        const int m_base = warp_m * 32;
        for (int c = 0; c < BNCH; ++c) {
            const int j = c + BDEPTH;
            if (j < BNCH) {
                wait_v(j);
                if (j >= BSTAGE) MBAR_WAIT(mbE + 8 * (j & 3), ((j >> 2) - 1) & 1);
                issue_chunk(j);
            } else {
                CP_COMMIT();
            }
            cp_wait<2>();
            if (c + 1 < BNCH) MBAR_ARRIVE(mbF + 8 * ((c + 1) & 3));

            MBAR_WAIT(mbF + 8 * (c & 3), (c >> 2) & 1);

            const int st = c & (BSTAGE - 1);
            const unsigned ps = sb + (st * B_STAGE_H + B_P_OFF) * 2;
            const unsigned es = sb + (st * B_STAGE_H + B_E_OFF) * 2;

#pragma unroll
            for (int ks = 0; ks < BKV / 16; ++ks) {
                unsigned a0[4], a1[4];
                ldsm4(a0[0], a0[1], a0[2], a0[3],
                      ps + ((m_base + (lane & 15)) * PP + ks * 16 + ((lane >> 4) << 3)) * 2);
                ldsm4(a1[0], a1[1], a1[2], a1[3],
                      ps + ((m_base + 16 + (lane & 15)) * PP + ks * 16 + ((lane >> 4) << 3)) * 2);
#pragma unroll
                for (int np = 0; np < 4; ++np) {
                    unsigned b0, b1, b2, b3;
                    ldsm4t(b0, b1, b2, b3,
                           es + ((ks * 16 + (lane & 15)) * EP + warp_n * 64 + np * 16 + ((lane >> 4) << 3)) * 2);
                    mma16816(hacc[0][np * 2],     a0, b0, b1);
                    mma16816(hacc[0][np * 2 + 1], a0, b2, b3);
                    mma16816(hacc[1][np * 2],     a1, b0, b1);
                    mma16816(hacc[1][np * 2 + 1], a1, b2, b3);
                }
            }
            MBAR_ARRIVE(mbE + 8 * (c & 3));
        }

        // epilogue: scale by 1/rowsum, store f32 (wm==250 guaranteed by wait_v(999))
        float inv[2][2];
#pragma unroll
        for (int mt = 0; mt < 2; ++mt) {
#pragma unroll
            for (int h = 0; h < 2; ++h)
                inv[mt][h] = 1.f / __ldg(&g_rsum[row_base + m_base + mt * 16 + (lane >> 2) + h * 8]);
        }
#pragma unroll
        for (int mt = 0; mt < 2; ++mt) {
            int r0 = row_base + m_base + mt * 16 + (lane >> 2);
#pragma unroll
            for (int nt = 0; nt < 8; ++nt) {
                int col = d_base + warp_n * 64 + nt * 8 + (lane & 3) * 2;
                float2 v0 = make_float2(hacc[mt][nt][0] * inv[mt][0], hacc[mt][nt][1] * inv[mt][0]);
                *(float2*)&out[(size_t)r0 * D_DIM + col] = v0;
                float2 v1 = make_float2(hacc[mt][nt][2] * inv[mt][1], hacc[mt][nt][3] * inv[mt][1]);
                *(float2*)&out[(size_t)(r0 + 8) * D_DIM + col] = v1;
            }
        }
    }
}

// ---------------- launch ----------------
extern "C" void kernel_launch(void* const* d_in, const int* in_sizes, int n_in,
                              void* d_out, int out_size) {
    const float* x   = (const float*)d_in[0];  // (4,64,256,32)
    const float* emb = (const float*)d_in[1];  // (32000,1024)
    const float* W   = (const float*)d_in[2];  // (256,32000)
    const float* b   = (const float*)d_in[3];  // (32000,)
    float* out = (float*)d_out;                // (4,2048,1024)

    cvt_w<<<dim3(V_TOT / 32, F_DIM / 32), dim3(32, 8)>>>(W);
    cvt_e<<<(V_TOT * (D_DIM / 4)) / 256, 256>>>((const float4*)emb);
    cvt_x<<<256, 256>>>(x);

    cudaFuncSetAttribute(fusedAB, cudaFuncAttributeMaxDynamicSharedMemorySize, U_SMEM_BYTES);
    fusedAB<<<NCTAS, 256, U_SMEM_BYTES>>>(b, out);
}

// round 15
// speedup vs baseline: 2.0453x; 2.0453x over previous
#include <cuda_runtime.h>
#include <cuda_fp16.h>
#include <cstdint>

#define V_TOT 32000
#define F_DIM 256
#define D_DIM 1024
#define R_TOT 8192

// pass A tiling: 128x128 tiles, 2 v-tiles per CTA, 8-slab continuous pipeline
#define AM 128
#define AV 128
#define ASLAB 64
#define ANSLAB (F_DIM / ASLAB)   // 4 slabs per tile
#define ANT 2                    // v-tiles per CTA
#define NSLAB (ANSLAB * ANT)     // 8
// pass B tiling (H = P @ E): 64x256 tiles, KV=32, 4 stages, mbarrier pipeline
#define BM 64
#define BD 256
#define BKV 32
#define BSTAGE 4
#define BDEPTH 3
#define BNCH (V_TOT / BKV)       // 1000

// ---- passA smem (halves) ----
#define AXP 72
#define A_STAGE_H (2 * AM * AXP)                  // 18432 halves per stage
#define A_P_OFF   (2 * A_STAGE_H)                 // 36864
#define APSP 136
#define A_SMEM_BYTES ((A_P_OFF + AM * APSP) * 2)  // 108,544 B -> 2 CTAs/SM

// ---- passB smem ----
#define PP 40                                     // 32 k + 8 pad (halves)
#define EP 264                                    // 256 d + 8 pad (halves)
#define B_STAGE_H (BM * PP + BKV * EP)            // 11008 halves = 22016 B
#define B_P_OFF 0
#define B_E_OFF (BM * PP)
#define B_MBAR_OFF (BSTAGE * B_STAGE_H * 2)       // 88064
#define B_SMEM_BYTES (B_MBAR_OFF + 128)           // + full[4], empty[4] mbarriers

// ---------------- static device scratch ----------------
__device__ __half g_W16[(size_t)V_TOT * F_DIM];   // (v, f) fp16
__device__ __half g_E16[(size_t)V_TOT * D_DIM];   // (v, d) fp16
__device__ __half g_X16[(size_t)R_TOT * F_DIM];   // (r, f) fp16 (permuted)
__device__ __half g_P[(size_t)R_TOT * V_TOT];     // (r, v) fp16 unnormalized probs
__device__ float  g_rsum[R_TOT];                  // per-row sum of exp

// ---------------- PTX helpers ----------------
__device__ __forceinline__ unsigned saddr(const void* p) {
    return (unsigned)__cvta_generic_to_shared(p);
}
__device__ __forceinline__ void ldsm4(unsigned& r0, unsigned& r1, unsigned& r2, unsigned& r3, unsigned a) {
    asm volatile("ldmatrix.sync.aligned.m8n8.x4.shared.b16 {%0,%1,%2,%3},[%4];"
                 : "=r"(r0), "=r"(r1), "=r"(r2), "=r"(r3) : "r"(a));
}
__device__ __forceinline__ void ldsm4t(unsigned& r0, unsigned& r1, unsigned& r2, unsigned& r3, unsigned a) {
    asm volatile("ldmatrix.sync.aligned.m8n8.x4.trans.shared.b16 {%0,%1,%2,%3},[%4];"
                 : "=r"(r0), "=r"(r1), "=r"(r2), "=r"(r3) : "r"(a));
}
__device__ __forceinline__ void mma16816(float* c, const unsigned* a, unsigned b0, unsigned b1) {
    asm volatile(
        "mma.sync.aligned.m16n8k16.row.col.f32.f16.f16.f32 "
        "{%0,%1,%2,%3},{%4,%5,%6,%7},{%8,%9},{%0,%1,%2,%3};"
        : "+f"(c[0]), "+f"(c[1]), "+f"(c[2]), "+f"(c[3])
        : "r"(a[0]), "r"(a[1]), "r"(a[2]), "r"(a[3]), "r"(b0), "r"(b1));
}
__device__ __forceinline__ void cp16(unsigned dst, const void* src) {
    asm volatile("cp.async.cg.shared.global [%0],[%1],16;" :: "r"(dst), "l"(src) : "memory");
}
#define CP_COMMIT() asm volatile("cp.async.commit_group;" ::: "memory")
template <int N> __device__ __forceinline__ void cp_wait() {
    asm volatile("cp.async.wait_group %0;" :: "n"(N) : "memory");
}

// mbarrier primitives
#define MBAR_INIT(a, n) \
    asm volatile("mbarrier.init.shared.b64 [%0], %1;" :: "r"(a), "r"(n) : "memory")
#define MBAR_ARRIVE(a) \
    asm volatile("mbarrier.arrive.shared.b64 _, [%0];" :: "r"(a) : "memory")
#define MBAR_WAIT(a, p) do {                                                            \
    asm volatile("{\n\t.reg .pred P1;\n\t"                                              \
        "W%=:\n\tmbarrier.try_wait.parity.acquire.cta.shared::cta.b64 P1, [%0], %1, 0x989680;\n\t" \
        "@P1 bra.uni D%=;\n\tbra.uni W%=;\n\tD%=:\n\t}"                                 \
        :: "r"((unsigned)(a)), "r"((unsigned)(p)) : "memory");                          \
} while (0)

// ---------------- prep kernels ----------------
__global__ void cvt_w(const float* __restrict__ W) {      // (f,v) f32 -> (v,f) f16
    __shared__ float t[32][33];
    int v0 = blockIdx.x * 32, f0 = blockIdx.y * 32;
    int tx = threadIdx.x, ty = threadIdx.y;  // (32,8)
#pragma unroll
    for (int k = 0; k < 32; k += 8)
        t[ty + k][tx] = W[(size_t)(f0 + ty + k) * V_TOT + v0 + tx];
    __syncthreads();
#pragma unroll
    for (int k = 0; k < 32; k += 8)
        g_W16[(size_t)(v0 + ty + k) * F_DIM + f0 + tx] = __float2half(t[tx][ty + k]);
}

__global__ void cvt_e(const float4* __restrict__ E) {     // (v,d) f32 -> (v,d) f16
    int i = blockIdx.x * blockDim.x + threadIdx.x;
    float4 v = E[i];
    __half2* dst = (__half2*)g_E16;
    dst[2 * (size_t)i]     = __floats2half2_rn(v.x, v.y);
    dst[2 * (size_t)i + 1] = __floats2half2_rn(v.z, v.w);
}

__global__ void cvt_x(const float* __restrict__ x) {      // (B,N,F,T) -> (r,f); also zeroes rsum
    __shared__ float sm[256][33];
    int bn = blockIdx.x;
    int b = bn >> 6, n = bn & 63;
    const float* src = x + ((size_t)b * 64 + n) * (F_DIM * 32);
    int tid = threadIdx.x;
#pragma unroll 4
    for (int i = tid; i < F_DIM * 32; i += 256) sm[i >> 5][i & 31] = src[i];
    __syncthreads();
#pragma unroll 4
    for (int t = 0; t < 32; ++t) {
        int r = b * 2048 + t * 64 + n;
        g_X16[(size_t)r * F_DIM + tid] = __float2half(sm[tid][t]);
    }
    if (tid < 32) g_rsum[b * 2048 + tid * 64 + n] = 0.f;
}

// ---------------- pass A: P = exp(X @ W^T + b), rowsum atomics ----------------
// grid (V_TOT/(AV*ANT) = 125, R_TOT/AM = 64), 256 threads, 2 CTAs/SM
// 2 v-tiles per CTA, continuous 8-slab pipeline; epilogue overlaps next slab load
__global__ void __launch_bounds__(256, 2)
passA(const float* __restrict__ bias) {
    extern __shared__ __align__(16) __half smem[];
    const unsigned sb = saddr(smem);
    const int tid  = threadIdx.x;
    const int lane = tid & 31;
    const int wid  = tid >> 5;
    const int warp_m = wid >> 1;    // 0..3 (32 rows)
    const int warp_n = wid & 1;     // 0..1 (64 cols)
    const int row_base = blockIdx.y * AM;
    const int v_base0  = blockIdx.x * (AV * ANT);

    const __half* Xsrc = g_X16 + (size_t)row_base * F_DIM;

    auto issue_slab = [&](int t) {
        const int st = t & 1;
        const unsigned xs = sb + (st * A_STAGE_H) * 2;
        const unsigned ws = xs + (AM * AXP) * 2;
        const int k0 = (t & 3) * ASLAB;
        const __half* Wsrc = g_W16 + (size_t)(v_base0 + (t >> 2) * AV) * F_DIM;
#pragma unroll
        for (int i = 0; i < 4; ++i) {
            int idx = tid + i * 256;
            int r = idx >> 3, sg = idx & 7;
            cp16(xs + (r * AXP + sg * 8) * 2, Xsrc + (size_t)r * F_DIM + k0 + sg * 8);
        }
#pragma unroll
        for (int i = 0; i < 4; ++i) {
            int idx = tid + i * 256;
            int r = idx >> 3, sg = idx & 7;
            cp16(ws + (r * AXP + sg * 8) * 2, Wsrc + (size_t)r * F_DIM + k0 + sg * 8);
        }
        CP_COMMIT();
    };

    float acc[2][8][4];
#pragma unroll
    for (int a = 0; a < 2; a++)
#pragma unroll
        for (int b = 0; b < 8; b++)
#pragma unroll
            for (int c = 0; c < 4; c++) acc[a][b][c] = 0.f;

    issue_slab(0);

    const int m_base = warp_m * 32;
    for (int t = 0; t < NSLAB; ++t) {
        cp_wait<0>();            // only slab t outstanding
        __syncthreads();
        if (t + 1 < NSLAB) issue_slab(t + 1);   // overlaps compute of t (and epilogue at t%4==3)

        const int st = t & 1;
        const unsigned xs = sb + (st * A_STAGE_H) * 2;
        const unsigned ws = xs + (AM * AXP) * 2;
#pragma unroll
        for (int ks = 0; ks < ASLAB / 16; ++ks) {
            unsigned a0[4], a1[4];
            ldsm4(a0[0], a0[1], a0[2], a0[3],
                  xs + ((m_base + (lane & 15)) * AXP + ks * 16 + ((lane >> 4) << 3)) * 2);
            ldsm4(a1[0], a1[1], a1[2], a1[3],
                  xs + ((m_base + 16 + (lane & 15)) * AXP + ks * 16 + ((lane >> 4) << 3)) * 2);
#pragma unroll
            for (int nb = 0; nb < 4; ++nb) {
                unsigned b0, b1, b2, b3;
                int wrow = warp_n * 64 + nb * 16 + ((lane >> 4) << 3) + (lane & 7);
                int koff = ks * 16 + (((lane >> 3) & 1) << 3);
                ldsm4(b0, b1, b2, b3, ws + (wrow * AXP + koff) * 2);
                mma16816(acc[0][nb * 2],     a0, b0, b1);
                mma16816(acc[0][nb * 2 + 1], a0, b2, b3);
                mma16816(acc[1][nb * 2],     a1, b0, b1);
                mma16816(acc[1][nb * 2 + 1], a1, b2, b3);
            }
        }

        if ((t & 3) == 3) {
            // ---- epilogue for tile t>>2 (overlaps the already-issued next slab load) ----
            const int v_base = v_base0 + (t >> 2) * AV;
            float rs[4] = {0.f, 0.f, 0.f, 0.f};
#pragma unroll
            for (int mt = 0; mt < 2; ++mt) {
                int r0 = m_base + mt * 16 + (lane >> 2);
#pragma unroll
                for (int nt = 0; nt < 8; ++nt) {
                    int c0 = warp_n * 64 + nt * 8 + (lane & 3) * 2;
                    float bv0 = __ldg(bias + v_base + c0);
                    float bv1 = __ldg(bias + v_base + c0 + 1);
                    float e0 = __expf(acc[mt][nt][0] + bv0);
                    float e1 = __expf(acc[mt][nt][1] + bv1);
                    __half2 h01 = __floats2half2_rn(e0, e1);
                    *(__half2*)(smem + A_P_OFF + r0 * APSP + c0) = h01;
                    rs[mt * 2] += __low2float(h01) + __high2float(h01);
                    float e2 = __expf(acc[mt][nt][2] + bv0);
                    float e3 = __expf(acc[mt][nt][3] + bv1);
                    __half2 h23 = __floats2half2_rn(e2, e3);
                    *(__half2*)(smem + A_P_OFF + (r0 + 8) * APSP + c0) = h23;
                    rs[mt * 2 + 1] += __low2float(h23) + __high2float(h23);
                }
            }
#pragma unroll
            for (int j = 0; j < 4; ++j) {
                rs[j] += __shfl_xor_sync(0xffffffffu, rs[j], 1);
                rs[j] += __shfl_xor_sync(0xffffffffu, rs[j], 2);
            }
            if ((lane & 3) == 0) {
#pragma unroll
                for (int j = 0; j < 4; ++j) {
                    int row = m_base + (j >> 1) * 16 + (lane >> 2) + (j & 1) * 8;
                    atomicAdd(&g_rsum[row_base + row], rs[j]);
                }
            }
            __syncthreads();
            // coalesced copy stage -> g_P
#pragma unroll
            for (int i = 0; i < 8; ++i) {
                int idx = tid + i * 256;
                int r = idx >> 4, s = idx & 15;
                *(uint4*)(g_P + (size_t)(row_base + r) * V_TOT + v_base + s * 8) =
                    *(const uint4*)(smem + A_P_OFF + r * APSP + s * 8);
            }
            // re-zero accumulators for next tile
#pragma unroll
            for (int a = 0; a < 2; a++)
#pragma unroll
                for (int b = 0; b < 8; b++)
#pragma unroll
                    for (int c = 0; c < 4; c++) acc[a][b][c] = 0.f;
        }
    }
}

// ---------------- pass B: H = (P @ E) / rowsum ----------------
// grid (D_DIM/BD = 4, R_TOT/BM = 128), 256 threads, 2 CTAs/SM
// mbarrier producer/consumer pipeline: no __syncthreads in the mainloop
__global__ void __launch_bounds__(256, 2)
passB(float* __restrict__ out) {
    extern __shared__ __align__(16) __half smem[];
    const unsigned sb = saddr(smem);
    const unsigned mbF = sb + B_MBAR_OFF;        // full[4]  at +0
    const unsigned mbE = sb + B_MBAR_OFF + 32;   // empty[4] at +32
    const int tid  = threadIdx.x;
    const int lane = tid & 31;
    const int wid  = tid >> 5;
    const int warp_m = wid >> 2;    // 0..1 (32 rows)
    const int warp_n = wid & 3;     // 0..3 (64 cols)
    const int row_base = blockIdx.y * BM;
    const int d_base   = blockIdx.x * BD;

    if (tid == 0) {
#pragma unroll
        for (int s = 0; s < BSTAGE; ++s) {
            MBAR_INIT(mbF + 8 * s, 256);
            MBAR_INIT(mbE + 8 * s, 256);
        }
    }
    __syncthreads();

    float hacc[2][8][4];
#pragma unroll
    for (int a = 0; a < 2; a++)
#pragma unroll
        for (int b = 0; b < 8; b++)
#pragma unroll
            for (int c = 0; c < 4; c++) hacc[a][b][c] = 0.f;

    auto issue_chunk = [&](int c) {
        const int st = c & (BSTAGE - 1);
        const unsigned ps = sb + (st * B_STAGE_H + B_P_OFF) * 2;
        const unsigned es = sb + (st * B_STAGE_H + B_E_OFF) * 2;
        const int v0 = c * BKV;
        // P: 64 rows x 4 segs (16B) = 256 segs
        {
            int r = tid >> 2, s = tid & 3;
            cp16(ps + (r * PP + s * 8) * 2, g_P + (size_t)(row_base + r) * V_TOT + v0 + s * 8);
        }
        // E: 32 rows x 32 segs = 1024 segs
#pragma unroll
        for (int i = 0; i < 4; ++i) {
            int idx = tid + i * 256;
            int r = idx >> 5, s = idx & 31;
            cp16(es + (r * EP + s * 8) * 2, g_E16 + (size_t)(v0 + r) * D_DIM + d_base + s * 8);
        }
        CP_COMMIT();
    };

    // prologue: stages 0..2, publish full[0]
    issue_chunk(0);
    issue_chunk(1);
    issue_chunk(2);
    cp_wait<2>();            // own share of chunk 0 landed
    MBAR_ARRIVE(mbF + 0);

    const int m_base = warp_m * 32;
    for (int c = 0; c < BNCH; ++c) {
        // producer: issue chunk c+3 (stage free once chunk c-1 consumed by all)
        const int j = c + BDEPTH;
        if (j < BNCH) {
            if (j >= BSTAGE) MBAR_WAIT(mbE + 8 * (j & 3), ((j >> 2) - 1) & 1);
            issue_chunk(j);
        } else {
            CP_COMMIT();     // keep group accounting uniform
        }
        cp_wait<2>();        // own share of chunk c+1 landed
        if (c + 1 < BNCH) MBAR_ARRIVE(mbF + 8 * ((c + 1) & 3));

        // consumer: chunk c
        MBAR_WAIT(mbF + 8 * (c & 3), (c >> 2) & 1);

        const int st = c & (BSTAGE - 1);
        const unsigned ps = sb + (st * B_STAGE_H + B_P_OFF) * 2;
        const unsigned es = sb + (st * B_STAGE_H + B_E_OFF) * 2;

#pragma unroll
        for (int ks = 0; ks < BKV / 16; ++ks) {
            unsigned a0[4], a1[4];
            ldsm4(a0[0], a0[1], a0[2], a0[3],
                  ps + ((m_base + (lane & 15)) * PP + ks * 16 + ((lane >> 4) << 3)) * 2);
            ldsm4(a1[0], a1[1], a1[2], a1[3],
                  ps + ((m_base + 16 + (lane & 15)) * PP + ks * 16 + ((lane >> 4) << 3)) * 2);
#pragma unroll
            for (int np = 0; np < 4; ++np) {
                unsigned b0, b1, b2, b3;
                ldsm4t(b0, b1, b2, b3,
                       es + ((ks * 16 + (lane & 15)) * EP + warp_n * 64 + np * 16 + ((lane >> 4) << 3)) * 2);
                mma16816(hacc[0][np * 2],     a0, b0, b1);
                mma16816(hacc[0][np * 2 + 1], a0, b2, b3);
                mma16816(hacc[1][np * 2],     a1, b0, b1);
                mma16816(hacc[1][np * 2 + 1], a1, b2, b3);
            }
        }
        MBAR_ARRIVE(mbE + 8 * (c & 3));
    }

    // epilogue: scale by 1/rowsum, store f32
    float inv[2][2];
#pragma unroll
    for (int mt = 0; mt < 2; ++mt) {
#pragma unroll
        for (int h = 0; h < 2; ++h)
            inv[mt][h] = 1.f / __ldg(&g_rsum[row_base + m_base + mt * 16 + (lane >> 2) + h * 8]);
    }
#pragma unroll
    for (int mt = 0; mt < 2; ++mt) {
        int r0 = row_base + m_base + mt * 16 + (lane >> 2);
#pragma unroll
        for (int nt = 0; nt < 8; ++nt) {
            int col = d_base + warp_n * 64 + nt * 8 + (lane & 3) * 2;
            float2 v0 = make_float2(hacc[mt][nt][0] * inv[mt][0], hacc[mt][nt][1] * inv[mt][0]);
            *(float2*)&out[(size_t)r0 * D_DIM + col] = v0;
            float2 v1 = make_float2(hacc[mt][nt][2] * inv[mt][1], hacc[mt][nt][3] * inv[mt][1]);
            *(float2*)&out[(size_t)(r0 + 8) * D_DIM + col] = v1;
        }
    }
}

// ---------------- launch ----------------
extern "C" void kernel_launch(void* const* d_in, const int* in_sizes, int n_in,
                              void* d_out, int out_size) {
    const float* x   = (const float*)d_in[0];  // (4,64,256,32)
    const float* emb = (const float*)d_in[1];  // (32000,1024)
    const float* W   = (const float*)d_in[2];  // (256,32000)
    const float* b   = (const float*)d_in[3];  // (32000,)
    float* out = (float*)d_out;                // (4,2048,1024)

    cvt_w<<<dim3(V_TOT / 32, F_DIM / 32), dim3(32, 8)>>>(W);
    cvt_e<<<(V_TOT * (D_DIM / 4)) / 256, 256>>>((const float4*)emb);
    cvt_x<<<256, 256>>>(x);

    cudaFuncSetAttribute(passA, cudaFuncAttributeMaxDynamicSharedMemorySize, A_SMEM_BYTES);
    passA<<<dim3(V_TOT / (AV * ANT), R_TOT / AM), 256, A_SMEM_BYTES>>>(b);

    cudaFuncSetAttribute(passB, cudaFuncAttributeMaxDynamicSharedMemorySize, B_SMEM_BYTES);
    passB<<<dim3(D_DIM / BD, R_TOT / BM), 256, B_SMEM_BYTES>>>(out);
}

// round 16
// speedup vs baseline: 2.0868x; 1.0203x over previous
#include <cuda_runtime.h>
#include <cuda_fp16.h>
#include <cstdint>

#define V_TOT 32000
#define F_DIM 256
#define D_DIM 1024
#define R_TOT 8192

// pass A tiling (S = X @ W^T, then exp -> P), k streamed in 4 slabs of 64
#define AM 128
#define AV 128
#define ASLAB 64
#define ANSLAB (F_DIM / ASLAB)   // 4
// pass B tiling (H = P @ E): 64x256 tiles, KV=32, 4 stages, mbarrier pipeline
#define BM 64
#define BD 256
#define BKV 32
#define BSTAGE 4
#define BDEPTH 3
#define BNCH (V_TOT / BKV)       // 1000

// ---- passA smem (halves) ----
#define AXP 72
#define A_STAGE_H (2 * AM * AXP)                  // 18432 halves per stage
#define A_P_OFF   (2 * A_STAGE_H)                 // 36864
#define APSP 136
#define A_SMEM_BYTES ((A_P_OFF + AM * APSP) * 2)  // 108,544 B -> 2 CTAs/SM

// ---- passB smem ----
#define PP 40                                     // 32 k + 8 pad (halves)
#define EP 264                                    // 256 d + 8 pad (halves)
#define B_STAGE_H (BM * PP + BKV * EP)            // 11008 halves = 22016 B
#define B_P_OFF 0
#define B_E_OFF (BM * PP)
#define B_MBAR_OFF (BSTAGE * B_STAGE_H * 2)       // 88064
#define B_SMEM_BYTES (B_MBAR_OFF + 128)           // + full[4], empty[4] mbarriers

// ---------------- static device scratch ----------------
__device__ __half g_W16[(size_t)V_TOT * F_DIM];   // (v, f) fp16
__device__ __half g_E16[(size_t)V_TOT * D_DIM];   // (v, d) fp16
__device__ __half g_X16[(size_t)R_TOT * F_DIM];   // (r, f) fp16 (permuted)
__device__ __half g_P[(size_t)R_TOT * V_TOT];     // (r, v) fp16 unnormalized probs
__device__ float  g_rsum[R_TOT];                  // per-row sum of exp

// ---------------- host-side aux (streams/events, created once at load) ----------------
struct AuxStreams {
    cudaStream_t s1;
    cudaEvent_t evFork, evJoin;
    AuxStreams() {
        cudaStreamCreateWithFlags(&s1, cudaStreamNonBlocking);
        cudaEventCreateWithFlags(&evFork, cudaEventDisableTiming);
        cudaEventCreateWithFlags(&evJoin, cudaEventDisableTiming);
    }
};
static AuxStreams g_aux;

// ---------------- PTX helpers ----------------
__device__ __forceinline__ unsigned saddr(const void* p) {
    return (unsigned)__cvta_generic_to_shared(p);
}
__device__ __forceinline__ void ldsm4(unsigned& r0, unsigned& r1, unsigned& r2, unsigned& r3, unsigned a) {
    asm volatile("ldmatrix.sync.aligned.m8n8.x4.shared.b16 {%0,%1,%2,%3},[%4];"
                 : "=r"(r0), "=r"(r1), "=r"(r2), "=r"(r3) : "r"(a));
}
__device__ __forceinline__ void ldsm4t(unsigned& r0, unsigned& r1, unsigned& r2, unsigned& r3, unsigned a) {
    asm volatile("ldmatrix.sync.aligned.m8n8.x4.trans.shared.b16 {%0,%1,%2,%3},[%4];"
                 : "=r"(r0), "=r"(r1), "=r"(r2), "=r"(r3) : "r"(a));
}
__device__ __forceinline__ void mma16816(float* c, const unsigned* a, unsigned b0, unsigned b1) {
    asm volatile(
        "mma.sync.aligned.m16n8k16.row.col.f32.f16.f16.f32 "
        "{%0,%1,%2,%3},{%4,%5,%6,%7},{%8,%9},{%0,%1,%2,%3};"
        : "+f"(c[0]), "+f"(c[1]), "+f"(c[2]), "+f"(c[3])
        : "r"(a[0]), "r"(a[1]), "r"(a[2]), "r"(a[3]), "r"(b0), "r"(b1));
}
__device__ __forceinline__ void cp16(unsigned dst, const void* src) {
    asm volatile("cp.async.cg.shared.global [%0],[%1],16;" :: "r"(dst), "l"(src) : "memory");
}
#define CP_COMMIT() asm volatile("cp.async.commit_group;" ::: "memory")
template <int N> __device__ __forceinline__ void cp_wait() {
    asm volatile("cp.async.wait_group %0;" :: "n"(N) : "memory");
}

// mbarrier primitives
#define MBAR_INIT(a, n) \
    asm volatile("mbarrier.init.shared.b64 [%0], %1;" :: "r"(a), "r"(n) : "memory")
#define MBAR_ARRIVE(a) \
    asm volatile("mbarrier.arrive.shared.b64 _, [%0];" :: "r"(a) : "memory")
#define MBAR_WAIT(a, p) do {                                                            \
    asm volatile("{\n\t.reg .pred P1;\n\t"                                              \
        "W%=:\n\tmbarrier.try_wait.parity.acquire.cta.shared::cta.b64 P1, [%0], %1, 0x989680;\n\t" \
        "@P1 bra.uni D%=;\n\tbra.uni W%=;\n\tD%=:\n\t}"                                 \
        :: "r"((unsigned)(a)), "r"((unsigned)(p)) : "memory");                          \
} while (0)

// ---------------- prep kernels ----------------
__global__ void cvt_w(const float* __restrict__ W) {      // (f,v) f32 -> (v,f) f16
    __shared__ float t[32][33];
    int v0 = blockIdx.x * 32, f0 = blockIdx.y * 32;
    int tx = threadIdx.x, ty = threadIdx.y;  // (32,8)
#pragma unroll
    for (int k = 0; k < 32; k += 8)
        t[ty + k][tx] = W[(size_t)(f0 + ty + k) * V_TOT + v0 + tx];
    __syncthreads();
#pragma unroll
    for (int k = 0; k < 32; k += 8)
        g_W16[(size_t)(v0 + ty + k) * F_DIM + f0 + tx] = __float2half(t[tx][ty + k]);
}

__global__ void cvt_e(const float4* __restrict__ E) {     // (v,d) f32 -> (v,d) f16
    int i = blockIdx.x * blockDim.x + threadIdx.x;
    float4 v = E[i];
    __half2* dst = (__half2*)g_E16;
    dst[2 * (size_t)i]     = __floats2half2_rn(v.x, v.y);
    dst[2 * (size_t)i + 1] = __floats2half2_rn(v.z, v.w);
}

__global__ void cvt_x(const float* __restrict__ x) {      // (B,N,F,T) -> (r,f); also zeroes rsum
    __shared__ float sm[256][33];
    int bn = blockIdx.x;
    int b = bn >> 6, n = bn & 63;
    const float* src = x + ((size_t)b * 64 + n) * (F_DIM * 32);
    int tid = threadIdx.x;
#pragma unroll 4
    for (int i = tid; i < F_DIM * 32; i += 256) sm[i >> 5][i & 31] = src[i];
    __syncthreads();
#pragma unroll 4
    for (int t = 0; t < 32; ++t) {
        int r = b * 2048 + t * 64 + n;
        g_X16[(size_t)r * F_DIM + tid] = __float2half(sm[tid][t]);
    }
    if (tid < 32) g_rsum[b * 2048 + tid * 64 + n] = 0.f;
}

// ---------------- pass A: P = exp(X @ W^T + b), rowsum atomics ----------------
// grid (V_TOT/AV = 250, R_TOT/AM = 64), 256 threads, 2 CTAs/SM, k slab-pipelined
__global__ void __launch_bounds__(256, 2)
passA(const float* __restrict__ bias) {
    extern __shared__ __align__(16) __half smem[];
    const unsigned sb = saddr(smem);
    const int tid  = threadIdx.x;
    const int lane = tid & 31;
    const int wid  = tid >> 5;
    const int warp_m = wid >> 1;    // 0..3 (32 rows)
    const int warp_n = wid & 1;     // 0..1 (64 cols)
    const int row_base = blockIdx.y * AM;
    const int v_base   = blockIdx.x * AV;

    const __half* Xsrc = g_X16 + (size_t)row_base * F_DIM;
    const __half* Wsrc = g_W16 + (size_t)v_base * F_DIM;

    auto issue_slab = [&](int s) {
        const int st = s & 1;
        const unsigned xs = sb + (st * A_STAGE_H) * 2;
        const unsigned ws = xs + (AM * AXP) * 2;
        const int k0 = s * ASLAB;
#pragma unroll
        for (int i = 0; i < 4; ++i) {
            int idx = tid + i * 256;
            int r = idx >> 3, sg = idx & 7;
            cp16(xs + (r * AXP + sg * 8) * 2, Xsrc + (size_t)r * F_DIM + k0 + sg * 8);
        }
#pragma unroll
        for (int i = 0; i < 4; ++i) {
            int idx = tid + i * 256;
            int r = idx >> 3, sg = idx & 7;
            cp16(ws + (r * AXP + sg * 8) * 2, Wsrc + (size_t)r * F_DIM + k0 + sg * 8);
        }
        CP_COMMIT();
    };

    float acc[2][8][4];
#pragma unroll
    for (int a = 0; a < 2; a++)
#pragma unroll
        for (int b = 0; b < 8; b++)
#pragma unroll
            for (int c = 0; c < 4; c++) acc[a][b][c] = 0.f;

    issue_slab(0);

    const int m_base = warp_m * 32;
#pragma unroll
    for (int s = 0; s < ANSLAB; ++s) {
        cp_wait<0>();
        __syncthreads();
        if (s + 1 < ANSLAB) issue_slab(s + 1);

        const int st = s & 1;
        const unsigned xs = sb + (st * A_STAGE_H) * 2;
        const unsigned ws = xs + (AM * AXP) * 2;
#pragma unroll
        for (int ks = 0; ks < ASLAB / 16; ++ks) {
            unsigned a0[4], a1[4];
            ldsm4(a0[0], a0[1], a0[2], a0[3],
                  xs + ((m_base + (lane & 15)) * AXP + ks * 16 + ((lane >> 4) << 3)) * 2);
            ldsm4(a1[0], a1[1], a1[2], a1[3],
                  xs + ((m_base + 16 + (lane & 15)) * AXP + ks * 16 + ((lane >> 4) << 3)) * 2);
#pragma unroll
            for (int nb = 0; nb < 4; ++nb) {
                unsigned b0, b1, b2, b3;
                int wrow = warp_n * 64 + nb * 16 + ((lane >> 4) << 3) + (lane & 7);
                int koff = ks * 16 + (((lane >> 3) & 1) << 3);
                ldsm4(b0, b1, b2, b3, ws + (wrow * AXP + koff) * 2);
                mma16816(acc[0][nb * 2],     a0, b0, b1);
                mma16816(acc[0][nb * 2 + 1], a0, b2, b3);
                mma16816(acc[1][nb * 2],     a1, b0, b1);
                mma16816(acc[1][nb * 2 + 1], a1, b2, b3);
            }
        }
    }
    __syncthreads();

    // exp -> fp16 stage + rowsum partials (sums from f16-rounded values)
    float rs[4] = {0.f, 0.f, 0.f, 0.f};
#pragma unroll
    for (int mt = 0; mt < 2; ++mt) {
        int r0 = m_base + mt * 16 + (lane >> 2);
#pragma unroll
        for (int nt = 0; nt < 8; ++nt) {
            int c0 = warp_n * 64 + nt * 8 + (lane & 3) * 2;
            float bv0 = __ldg(bias + v_base + c0);
            float bv1 = __ldg(bias + v_base + c0 + 1);
            float e0 = __expf(acc[mt][nt][0] + bv0);
            float e1 = __expf(acc[mt][nt][1] + bv1);
            __half2 h01 = __floats2half2_rn(e0, e1);
            *(__half2*)(smem + A_P_OFF + r0 * APSP + c0) = h01;
            rs[mt * 2] += __low2float(h01) + __high2float(h01);
            float e2 = __expf(acc[mt][nt][2] + bv0);
            float e3 = __expf(acc[mt][nt][3] + bv1);
            __half2 h23 = __floats2half2_rn(e2, e3);
            *(__half2*)(smem + A_P_OFF + (r0 + 8) * APSP + c0) = h23;
            rs[mt * 2 + 1] += __low2float(h23) + __high2float(h23);
        }
    }
#pragma unroll
    for (int j = 0; j < 4; ++j) {
        rs[j] += __shfl_xor_sync(0xffffffffu, rs[j], 1);
        rs[j] += __shfl_xor_sync(0xffffffffu, rs[j], 2);
    }
    if ((lane & 3) == 0) {
#pragma unroll
        for (int j = 0; j < 4; ++j) {
            int row = m_base + (j >> 1) * 16 + (lane >> 2) + (j & 1) * 8;
            atomicAdd(&g_rsum[row_base + row], rs[j]);
        }
    }
    __syncthreads();

    // coalesced copy stage -> g_P
#pragma unroll
    for (int i = 0; i < 8; ++i) {
        int idx = tid + i * 256;                // 2048 segs of 16B
        int r = idx >> 4, s = idx & 15;
        *(uint4*)(g_P + (size_t)(row_base + r) * V_TOT + v_base + s * 8) =
            *(const uint4*)(smem + A_P_OFF + r * APSP + s * 8);
    }
}

// ---------------- pass B: H = (P @ E) / rowsum ----------------
// grid (D_DIM/BD = 4, R_TOT/BM = 128), 256 threads, 2 CTAs/SM
// mbarrier producer/consumer pipeline: no __syncthreads in the mainloop
__global__ void __launch_bounds__(256, 2)
passB(float* __restrict__ out) {
    extern __shared__ __align__(16) __half smem[];
    const unsigned sb = saddr(smem);
    const unsigned mbF = sb + B_MBAR_OFF;        // full[4]  at +0
    const unsigned mbE = sb + B_MBAR_OFF + 32;   // empty[4] at +32
    const int tid  = threadIdx.x;
    const int lane = tid & 31;
    const int wid  = tid >> 5;
    const int warp_m = wid >> 2;    // 0..1 (32 rows)
    const int warp_n = wid & 3;     // 0..3 (64 cols)
    const int row_base = blockIdx.y * BM;
    const int d_base   = blockIdx.x * BD;

    if (tid == 0) {
#pragma unroll
        for (int s = 0; s < BSTAGE; ++s) {
            MBAR_INIT(mbF + 8 * s, 256);
            MBAR_INIT(mbE + 8 * s, 256);
        }
    }
    __syncthreads();

    float hacc[2][8][4];
#pragma unroll
    for (int a = 0; a < 2; a++)
#pragma unroll
        for (int b = 0; b < 8; b++)
#pragma unroll
            for (int c = 0; c < 4; c++) hacc[a][b][c] = 0.f;

    auto issue_chunk = [&](int c) {
        const int st = c & (BSTAGE - 1);
        const unsigned ps = sb + (st * B_STAGE_H + B_P_OFF) * 2;
        const unsigned es = sb + (st * B_STAGE_H + B_E_OFF) * 2;
        const int v0 = c * BKV;
        // P: 64 rows x 4 segs (16B) = 256 segs
        {
            int r = tid >> 2, s = tid & 3;
            cp16(ps + (r * PP + s * 8) * 2, g_P + (size_t)(row_base + r) * V_TOT + v0 + s * 8);
        }
        // E: 32 rows x 32 segs = 1024 segs
#pragma unroll
        for (int i = 0; i < 4; ++i) {
            int idx = tid + i * 256;
            int r = idx >> 5, s = idx & 31;
            cp16(es + (r * EP + s * 8) * 2, g_E16 + (size_t)(v0 + r) * D_DIM + d_base + s * 8);
        }
        CP_COMMIT();
    };

    // prologue: stages 0..2, publish full[0]
    issue_chunk(0);
    issue_chunk(1);
    issue_chunk(2);
    cp_wait<2>();            // own share of chunk 0 landed
    MBAR_ARRIVE(mbF + 0);

    const int m_base = warp_m * 32;
    for (int c = 0; c < BNCH; ++c) {
        // producer: issue chunk c+3 (stage free once chunk c-1 consumed by all)
        const int j = c + BDEPTH;
        if (j < BNCH) {
            if (j >= BSTAGE) MBAR_WAIT(mbE + 8 * (j & 3), ((j >> 2) - 1) & 1);
            issue_chunk(j);
        } else {
            CP_COMMIT();     // keep group accounting uniform
        }
        cp_wait<2>();        // own share of chunk c+1 landed
        if (c + 1 < BNCH) MBAR_ARRIVE(mbF + 8 * ((c + 1) & 3));

        // consumer: chunk c
        MBAR_WAIT(mbF + 8 * (c & 3), (c >> 2) & 1);

        const int st = c & (BSTAGE - 1);
        const unsigned ps = sb + (st * B_STAGE_H + B_P_OFF) * 2;
        const unsigned es = sb + (st * B_STAGE_H + B_E_OFF) * 2;

#pragma unroll
        for (int ks = 0; ks < BKV / 16; ++ks) {
            unsigned a0[4], a1[4];
            ldsm4(a0[0], a0[1], a0[2], a0[3],
                  ps + ((m_base + (lane & 15)) * PP + ks * 16 + ((lane >> 4) << 3)) * 2);
            ldsm4(a1[0], a1[1], a1[2], a1[3],
                  ps + ((m_base + 16 + (lane & 15)) * PP + ks * 16 + ((lane >> 4) << 3)) * 2);
#pragma unroll
            for (int np = 0; np < 4; ++np) {
                unsigned b0, b1, b2, b3;
                ldsm4t(b0, b1, b2, b3,
                       es + ((ks * 16 + (lane & 15)) * EP + warp_n * 64 + np * 16 + ((lane >> 4) << 3)) * 2);
                mma16816(hacc[0][np * 2],     a0, b0, b1);
                mma16816(hacc[0][np * 2 + 1], a0, b2, b3);
                mma16816(hacc[1][np * 2],     a1, b0, b1);
                mma16816(hacc[1][np * 2 + 1], a1, b2, b3);
            }
        }
        MBAR_ARRIVE(mbE + 8 * (c & 3));
    }

    // epilogue: scale by 1/rowsum, store f32
    float inv[2][2];
#pragma unroll
    for (int mt = 0; mt < 2; ++mt) {
#pragma unroll
        for (int h = 0; h < 2; ++h)
            inv[mt][h] = 1.f / __ldg(&g_rsum[row_base + m_base + mt * 16 + (lane >> 2) + h * 8]);
    }
#pragma unroll
    for (int mt = 0; mt < 2; ++mt) {
        int r0 = row_base + m_base + mt * 16 + (lane >> 2);
#pragma unroll
        for (int nt = 0; nt < 8; ++nt) {
            int col = d_base + warp_n * 64 + nt * 8 + (lane & 3) * 2;
            float2 v0 = make_float2(hacc[mt][nt][0] * inv[mt][0], hacc[mt][nt][1] * inv[mt][0]);
            *(float2*)&out[(size_t)r0 * D_DIM + col] = v0;
            float2 v1 = make_float2(hacc[mt][nt][2] * inv[mt][1], hacc[mt][nt][3] * inv[mt][1]);
            *(float2*)&out[(size_t)(r0 + 8) * D_DIM + col] = v1;
        }
    }
}

// ---------------- launch ----------------
extern "C" void kernel_launch(void* const* d_in, const int* in_sizes, int n_in,
                              void* d_out, int out_size) {
    const float* x   = (const float*)d_in[0];  // (4,64,256,32)
    const float* emb = (const float*)d_in[1];  // (32000,1024)
    const float* W   = (const float*)d_in[2];  // (256,32000)
    const float* b   = (const float*)d_in[3];  // (32000,)
    float* out = (float*)d_out;                // (4,2048,1024)

    // fork: cvt_e on side stream, concurrent with cvt_w/cvt_x/passA
    cudaEventRecord(g_aux.evFork, 0);
    cudaStreamWaitEvent(g_aux.s1, g_aux.evFork, 0);
    cvt_e<<<(V_TOT * (D_DIM / 4)) / 256, 256, 0, g_aux.s1>>>((const float4*)emb);
    cudaEventRecord(g_aux.evJoin, g_aux.s1);

    cvt_w<<<dim3(V_TOT / 32, F_DIM / 32), dim3(32, 8)>>>(W);
    cvt_x<<<256, 256>>>(x);

    cudaFuncSetAttribute(passA, cudaFuncAttributeMaxDynamicSharedMemorySize, A_SMEM_BYTES);
    passA<<<dim3(V_TOT / AV, R_TOT / AM), 256, A_SMEM_BYTES>>>(b);

    // join: passB needs g_E16
    cudaStreamWaitEvent(0, g_aux.evJoin, 0);
    cudaFuncSetAttribute(passB, cudaFuncAttributeMaxDynamicSharedMemorySize, B_SMEM_BYTES);
    passB<<<dim3(D_DIM / BD, R_TOT / BM), 256, B_SMEM_BYTES>>>(out);
}

// round 17
// speedup vs baseline: 2.1893x; 1.0491x over previous
#include <cuda_runtime.h>
#include <cuda_fp16.h>
#include <cstdint>

#define V_TOT 32000
#define F_DIM 256
#define D_DIM 1024
#define R_TOT 8192

// pass A tiling (S = X @ W^T, then exp -> P), k streamed in 4 slabs of 64
#define AM 128
#define AV 128
#define ASLAB 64
#define ANSLAB (F_DIM / ASLAB)   // 4
// pass B tiling (H = P @ E): 64x256 tiles, KV=32, 4 stages, mbarrier pipeline
// persistent: 296 CTAs, balanced global chunk ranges, k-split w/ atomic flush
#define BM 64
#define BD 256
#define BKV 32
#define BSTAGE 4
#define BDEPTH 3
#define NTILES ((R_TOT / BM) * (D_DIM / BD))   // 128*4 = 512
#define CPT (V_TOT / BKV)                      // 1000 chunks per tile
#define GUNITS (NTILES * CPT)                  // 512000
#define NPERS 296                              // 148 SMs x 2 CTAs

// ---- passA smem (halves) ----
#define AXP 72
#define A_STAGE_H (2 * AM * AXP)                  // 18432 halves per stage
#define A_P_OFF   (2 * A_STAGE_H)                 // 36864
#define APSP 136
#define A_SMEM_BYTES ((A_P_OFF + AM * APSP) * 2)  // 108,544 B -> 2 CTAs/SM

// ---- passB smem ----
#define PP 40                                     // 32 k + 8 pad (halves)
#define EP 264                                    // 256 d + 8 pad (halves)
#define B_STAGE_H (BM * PP + BKV * EP)            // 11008 halves = 22016 B
#define B_P_OFF 0
#define B_E_OFF (BM * PP)
#define B_MBAR_OFF (BSTAGE * B_STAGE_H * 2)       // 88064
#define B_SMEM_BYTES (B_MBAR_OFF + 128)           // + full[4], empty[4] mbarriers

// ---------------- static device scratch ----------------
__device__ __half g_W16[(size_t)V_TOT * F_DIM];   // (v, f) fp16
__device__ __half g_E16[(size_t)V_TOT * D_DIM];   // (v, d) fp16
__device__ __half g_X16[(size_t)R_TOT * F_DIM];   // (r, f) fp16 (permuted)
__device__ __half g_P[(size_t)R_TOT * V_TOT];     // (r, v) fp16 unnormalized probs
__device__ float  g_rsum[R_TOT];                  // per-row sum of exp
__device__ float  g_H[(size_t)R_TOT * D_DIM];     // unnormalized H accumulator (f32)

// ---------------- host-side aux (streams/events, created once at load) ----------------
struct AuxStreams {
    cudaStream_t s1;
    cudaEvent_t evFork, evJoin;
    AuxStreams() {
        cudaStreamCreateWithFlags(&s1, cudaStreamNonBlocking);
        cudaEventCreateWithFlags(&evFork, cudaEventDisableTiming);
        cudaEventCreateWithFlags(&evJoin, cudaEventDisableTiming);
    }
};
static AuxStreams g_aux;

// ---------------- PTX helpers ----------------
__device__ __forceinline__ unsigned saddr(const void* p) {
    return (unsigned)__cvta_generic_to_shared(p);
}
__device__ __forceinline__ void ldsm4(unsigned& r0, unsigned& r1, unsigned& r2, unsigned& r3, unsigned a) {
    asm volatile("ldmatrix.sync.aligned.m8n8.x4.shared.b16 {%0,%1,%2,%3},[%4];"
                 : "=r"(r0), "=r"(r1), "=r"(r2), "=r"(r3) : "r"(a));
}
__device__ __forceinline__ void ldsm4t(unsigned& r0, unsigned& r1, unsigned& r2, unsigned& r3, unsigned a) {
    asm volatile("ldmatrix.sync.aligned.m8n8.x4.trans.shared.b16 {%0,%1,%2,%3},[%4];"
                 : "=r"(r0), "=r"(r1), "=r"(r2), "=r"(r3) : "r"(a));
}
__device__ __forceinline__ void mma16816(float* c, const unsigned* a, unsigned b0, unsigned b1) {
    asm volatile(
        "mma.sync.aligned.m16n8k16.row.col.f32.f16.f16.f32 "
        "{%0,%1,%2,%3},{%4,%5,%6,%7},{%8,%9},{%0,%1,%2,%3};"
        : "+f"(c[0]), "+f"(c[1]), "+f"(c[2]), "+f"(c[3])
        : "r"(a[0]), "r"(a[1]), "r"(a[2]), "r"(a[3]), "r"(b0), "r"(b1));
}
__device__ __forceinline__ void cp16(unsigned dst, const void* src) {
    asm volatile("cp.async.cg.shared.global [%0],[%1],16;" :: "r"(dst), "l"(src) : "memory");
}
#define CP_COMMIT() asm volatile("cp.async.commit_group;" ::: "memory")
template <int N> __device__ __forceinline__ void cp_wait() {
    asm volatile("cp.async.wait_group %0;" :: "n"(N) : "memory");
}

// mbarrier primitives
#define MBAR_INIT(a, n) \
    asm volatile("mbarrier.init.shared.b64 [%0], %1;" :: "r"(a), "r"(n) : "memory")
#define MBAR_ARRIVE(a) \
    asm volatile("mbarrier.arrive.shared.b64 _, [%0];" :: "r"(a) : "memory")
#define MBAR_WAIT(a, p) do {                                                            \
    asm volatile("{\n\t.reg .pred P1;\n\t"                                              \
        "W%=:\n\tmbarrier.try_wait.parity.acquire.cta.shared::cta.b64 P1, [%0], %1, 0x989680;\n\t" \
        "@P1 bra.uni D%=;\n\tbra.uni W%=;\n\tD%=:\n\t}"                                 \
        :: "r"((unsigned)(a)), "r"((unsigned)(p)) : "memory");                          \
} while (0)

// ---------------- prep kernels ----------------
__global__ void cvt_w(const float* __restrict__ W) {      // (f,v) f32 -> (v,f) f16
    __shared__ float t[32][33];
    int v0 = blockIdx.x * 32, f0 = blockIdx.y * 32;
    int tx = threadIdx.x, ty = threadIdx.y;  // (32,8)
#pragma unroll
    for (int k = 0; k < 32; k += 8)
        t[ty + k][tx] = W[(size_t)(f0 + ty + k) * V_TOT + v0 + tx];
    __syncthreads();
#pragma unroll
    for (int k = 0; k < 32; k += 8)
        g_W16[(size_t)(v0 + ty + k) * F_DIM + f0 + tx] = __float2half(t[tx][ty + k]);
}

__global__ void cvt_e(const float4* __restrict__ E) {     // (v,d) f32 -> (v,d) f16
    int i = blockIdx.x * blockDim.x + threadIdx.x;
    float4 v = E[i];
    __half2* dst = (__half2*)g_E16;
    dst[2 * (size_t)i]     = __floats2half2_rn(v.x, v.y);
    dst[2 * (size_t)i + 1] = __floats2half2_rn(v.z, v.w);
}

__global__ void zero_H() {                                // zero g_H (f32 accumulators)
    int i = blockIdx.x * 256 + threadIdx.x;               // float4 index
    ((float4*)g_H)[i] = make_float4(0.f, 0.f, 0.f, 0.f);
}

__global__ void cvt_x(const float* __restrict__ x) {      // (B,N,F,T) -> (r,f); also zeroes rsum
    __shared__ float sm[256][33];
    int bn = blockIdx.x;
    int b = bn >> 6, n = bn & 63;
    const float* src = x + ((size_t)b * 64 + n) * (F_DIM * 32);
    int tid = threadIdx.x;
#pragma unroll 4
    for (int i = tid; i < F_DIM * 32; i += 256) sm[i >> 5][i & 31] = src[i];
    __syncthreads();
#pragma unroll 4
    for (int t = 0; t < 32; ++t) {
        int r = b * 2048 + t * 64 + n;
        g_X16[(size_t)r * F_DIM + tid] = __float2half(sm[tid][t]);
    }
    if (tid < 32) g_rsum[b * 2048 + tid * 64 + n] = 0.f;
}

// ---------------- pass A: P = exp(X @ W^T + b), rowsum atomics ----------------
// grid (V_TOT/AV = 250, R_TOT/AM = 64), 256 threads, 2 CTAs/SM, k slab-pipelined
__global__ void __launch_bounds__(256, 2)
passA(const float* __restrict__ bias) {
    extern __shared__ __align__(16) __half smem[];
    const unsigned sb = saddr(smem);
    const int tid  = threadIdx.x;
    const int lane = tid & 31;
    const int wid  = tid >> 5;
    const int warp_m = wid >> 1;    // 0..3 (32 rows)
    const int warp_n = wid & 1;     // 0..1 (64 cols)
    const int row_base = blockIdx.y * AM;
    const int v_base   = blockIdx.x * AV;

    const __half* Xsrc = g_X16 + (size_t)row_base * F_DIM;
    const __half* Wsrc = g_W16 + (size_t)v_base * F_DIM;

    auto issue_slab = [&](int s) {
        const int st = s & 1;
        const unsigned xs = sb + (st * A_STAGE_H) * 2;
        const unsigned ws = xs + (AM * AXP) * 2;
        const int k0 = s * ASLAB;
#pragma unroll
        for (int i = 0; i < 4; ++i) {
            int idx = tid + i * 256;
            int r = idx >> 3, sg = idx & 7;
            cp16(xs + (r * AXP + sg * 8) * 2, Xsrc + (size_t)r * F_DIM + k0 + sg * 8);
        }
#pragma unroll
        for (int i = 0; i < 4; ++i) {
            int idx = tid + i * 256;
            int r = idx >> 3, sg = idx & 7;
            cp16(ws + (r * AXP + sg * 8) * 2, Wsrc + (size_t)r * F_DIM + k0 + sg * 8);
        }
        CP_COMMIT();
    };

    float acc[2][8][4];
#pragma unroll
    for (int a = 0; a < 2; a++)
#pragma unroll
        for (int b = 0; b < 8; b++)
#pragma unroll
            for (int c = 0; c < 4; c++) acc[a][b][c] = 0.f;

    issue_slab(0);

    const int m_base = warp_m * 32;
#pragma unroll
    for (int s = 0; s < ANSLAB; ++s) {
        cp_wait<0>();
        __syncthreads();
        if (s + 1 < ANSLAB) issue_slab(s + 1);

        const int st = s & 1;
        const unsigned xs = sb + (st * A_STAGE_H) * 2;
        const unsigned ws = xs + (AM * AXP) * 2;
#pragma unroll
        for (int ks = 0; ks < ASLAB / 16; ++ks) {
            unsigned a0[4], a1[4];
            ldsm4(a0[0], a0[1], a0[2], a0[3],
                  xs + ((m_base + (lane & 15)) * AXP + ks * 16 + ((lane >> 4) << 3)) * 2);
            ldsm4(a1[0], a1[1], a1[2], a1[3],
                  xs + ((m_base + 16 + (lane & 15)) * AXP + ks * 16 + ((lane >> 4) << 3)) * 2);
#pragma unroll
            for (int nb = 0; nb < 4; ++nb) {
                unsigned b0, b1, b2, b3;
                int wrow = warp_n * 64 + nb * 16 + ((lane >> 4) << 3) + (lane & 7);
                int koff = ks * 16 + (((lane >> 3) & 1) << 3);
                ldsm4(b0, b1, b2, b3, ws + (wrow * AXP + koff) * 2);
                mma16816(acc[0][nb * 2],     a0, b0, b1);
                mma16816(acc[0][nb * 2 + 1], a0, b2, b3);
                mma16816(acc[1][nb * 2],     a1, b0, b1);
                mma16816(acc[1][nb * 2 + 1], a1, b2, b3);
            }
        }
    }
    __syncthreads();

    // exp -> fp16 stage + rowsum partials (sums from f16-rounded values)
    float rs[4] = {0.f, 0.f, 0.f, 0.f};
#pragma unroll
    for (int mt = 0; mt < 2; ++mt) {
        int r0 = m_base + mt * 16 + (lane >> 2);
#pragma unroll
        for (int nt = 0; nt < 8; ++nt) {
            int c0 = warp_n * 64 + nt * 8 + (lane & 3) * 2;
            float bv0 = __ldg(bias + v_base + c0);
            float bv1 = __ldg(bias + v_base + c0 + 1);
            float e0 = __expf(acc[mt][nt][0] + bv0);
            float e1 = __expf(acc[mt][nt][1] + bv1);
            __half2 h01 = __floats2half2_rn(e0, e1);
            *(__half2*)(smem + A_P_OFF + r0 * APSP + c0) = h01;
            rs[mt * 2] += __low2float(h01) + __high2float(h01);
            float e2 = __expf(acc[mt][nt][2] + bv0);
            float e3 = __expf(acc[mt][nt][3] + bv1);
            __half2 h23 = __floats2half2_rn(e2, e3);
            *(__half2*)(smem + A_P_OFF + (r0 + 8) * APSP + c0) = h23;
            rs[mt * 2 + 1] += __low2float(h23) + __high2float(h23);
        }
    }
#pragma unroll
    for (int j = 0; j < 4; ++j) {
        rs[j] += __shfl_xor_sync(0xffffffffu, rs[j], 1);
        rs[j] += __shfl_xor_sync(0xffffffffu, rs[j], 2);
    }
    if ((lane & 3) == 0) {
#pragma unroll
        for (int j = 0; j < 4; ++j) {
            int row = m_base + (j >> 1) * 16 + (lane >> 2) + (j & 1) * 8;
            atomicAdd(&g_rsum[row_base + row], rs[j]);
        }
    }
    __syncthreads();

    // coalesced copy stage -> g_P
#pragma unroll
    for (int i = 0; i < 8; ++i) {
        int idx = tid + i * 256;                // 2048 segs of 16B
        int r = idx >> 4, s = idx & 15;
        *(uint4*)(g_P + (size_t)(row_base + r) * V_TOT + v_base + s * 8) =
            *(const uint4*)(smem + A_P_OFF + r * APSP + s * 8);
    }
}

// ---------------- pass B: g_H += P @ E (persistent, balanced, k-split) ----------------
// grid NPERS=296, 256 threads, 2 CTAs/SM; mbarrier pipeline over a contiguous
// range of global chunk-units; hacc flushed to g_H via atomicAdd at tile edges
__global__ void __launch_bounds__(256, 2)
passB() {
    extern __shared__ __align__(16) __half smem[];
    const unsigned sb = saddr(smem);
    const unsigned mbF = sb + B_MBAR_OFF;        // full[4]
    const unsigned mbE = sb + B_MBAR_OFF + 32;   // empty[4]
    const int tid  = threadIdx.x;
    const int lane = tid & 31;
    const int wid  = tid >> 5;
    const int warp_m = wid >> 2;    // 0..1 (32 rows)
    const int warp_n = wid & 3;     // 0..3 (64 cols)

    if (tid == 0) {
#pragma unroll
        for (int s = 0; s < BSTAGE; ++s) {
            MBAR_INIT(mbF + 8 * s, 256);
            MBAR_INIT(mbE + 8 * s, 256);
        }
    }
    __syncthreads();

    const int start = (int)(((long long)blockIdx.x * GUNITS) / NPERS);
    const int end   = (int)(((long long)(blockIdx.x + 1) * GUNITS) / NPERS);

    float hacc[2][8][4];
#pragma unroll
    for (int a = 0; a < 2; a++)
#pragma unroll
        for (int b = 0; b < 8; b++)
#pragma unroll
            for (int c = 0; c < 4; c++) hacc[a][b][c] = 0.f;

    auto issue_chunk = [&](int u, int l) {    // u = global unit, l = local index
        const int t  = u / CPT;
        const int ck = u - t * CPT;
        const int row_base = (t >> 2) * BM;
        const int d_base   = (t & 3) * BD;
        const int v0 = ck * BKV;
        const int st = l & (BSTAGE - 1);
        const unsigned ps = sb + (st * B_STAGE_H + B_P_OFF) * 2;
        const unsigned es = sb + (st * B_STAGE_H + B_E_OFF) * 2;
        // P: 64 rows x 4 segs (16B)
        {
            int r = tid >> 2, s = tid & 3;
            cp16(ps + (r * PP + s * 8) * 2, g_P + (size_t)(row_base + r) * V_TOT + v0 + s * 8);
        }
        // E: 32 rows x 32 segs
#pragma unroll
        for (int i = 0; i < 4; ++i) {
            int idx = tid + i * 256;
            int r = idx >> 5, s = idx & 31;
            cp16(es + (r * EP + s * 8) * 2, g_E16 + (size_t)(v0 + r) * D_DIM + d_base + s * 8);
        }
        CP_COMMIT();
    };

    // prologue: first 3 chunks of the range, publish full[0]
    issue_chunk(start, 0);
    issue_chunk(start + 1, 1);
    issue_chunk(start + 2, 2);
    cp_wait<2>();
    MBAR_ARRIVE(mbF + 0);

    const int m_base = warp_m * 32;
    int cur_tile = start / CPT;

    for (int u = start; u < end; ++u) {
        const int l  = u - start;
        const int lj = l + BDEPTH;
        if (u + BDEPTH < end) {
            if (lj >= BSTAGE) MBAR_WAIT(mbE + 8 * (lj & 3), ((lj >> 2) - 1) & 1);
            issue_chunk(u + BDEPTH, lj);
        } else {
            CP_COMMIT();     // keep group accounting uniform
        }
        cp_wait<2>();
        if (u + 1 < end) MBAR_ARRIVE(mbF + 8 * ((l + 1) & 3));

        MBAR_WAIT(mbF + 8 * (l & 3), (l >> 2) & 1);

        const int st = l & (BSTAGE - 1);
        const unsigned ps = sb + (st * B_STAGE_H + B_P_OFF) * 2;
        const unsigned es = sb + (st * B_STAGE_H + B_E_OFF) * 2;

#pragma unroll
        for (int ks = 0; ks < BKV / 16; ++ks) {
            unsigned a0[4], a1[4];
            ldsm4(a0[0], a0[1], a0[2], a0[3],
                  ps + ((m_base + (lane & 15)) * PP + ks * 16 + ((lane >> 4) << 3)) * 2);
            ldsm4(a1[0], a1[1], a1[2], a1[3],
                  ps + ((m_base + 16 + (lane & 15)) * PP + ks * 16 + ((lane >> 4) << 3)) * 2);
#pragma unroll
            for (int np = 0; np < 4; ++np) {
                unsigned b0, b1, b2, b3;
                ldsm4t(b0, b1, b2, b3,
                       es + ((ks * 16 + (lane & 15)) * EP + warp_n * 64 + np * 16 + ((lane >> 4) << 3)) * 2);
                mma16816(hacc[0][np * 2],     a0, b0, b1);
                mma16816(hacc[0][np * 2 + 1], a0, b2, b3);
                mma16816(hacc[1][np * 2],     a1, b0, b1);
                mma16816(hacc[1][np * 2 + 1], a1, b2, b3);
            }
        }
        MBAR_ARRIVE(mbE + 8 * (l & 3));

        // flush at tile boundary / range end
        const int next_tile = (u + 1 < end) ? (u + 1) / CPT : -1;
        if (next_tile != cur_tile) {
            const int row_base = (cur_tile >> 2) * BM;
            const int d_base   = (cur_tile & 3) * BD;
#pragma unroll
            for (int mt = 0; mt < 2; ++mt) {
                int r0 = row_base + m_base + mt * 16 + (lane >> 2);
#pragma unroll
                for (int nt = 0; nt < 8; ++nt) {
                    int col = d_base + warp_n * 64 + nt * 8 + (lane & 3) * 2;
                    atomicAdd(&g_H[(size_t)r0 * D_DIM + col],       hacc[mt][nt][0]);
                    atomicAdd(&g_H[(size_t)r0 * D_DIM + col + 1],   hacc[mt][nt][1]);
                    atomicAdd(&g_H[(size_t)(r0 + 8) * D_DIM + col],     hacc[mt][nt][2]);
                    atomicAdd(&g_H[(size_t)(r0 + 8) * D_DIM + col + 1], hacc[mt][nt][3]);
                    hacc[mt][nt][0] = hacc[mt][nt][1] = hacc[mt][nt][2] = hacc[mt][nt][3] = 0.f;
                }
            }
            cur_tile = next_tile;
        }
    }
}

// ---------------- scale: out = g_H / rsum ----------------
__global__ void scaleH(float4* __restrict__ out) {
    int i = blockIdx.x * 256 + threadIdx.x;   // float4 index; 256 float4 per row
    float4 h = ((const float4*)g_H)[i];
    float inv = 1.f / __ldg(&g_rsum[i >> 8]);
    out[i] = make_float4(h.x * inv, h.y * inv, h.z * inv, h.w * inv);
}

// ---------------- launch ----------------
extern "C" void kernel_launch(void* const* d_in, const int* in_sizes, int n_in,
                              void* d_out, int out_size) {
    const float* x   = (const float*)d_in[0];  // (4,64,256,32)
    const float* emb = (const float*)d_in[1];  // (32000,1024)
    const float* W   = (const float*)d_in[2];  // (256,32000)
    const float* b   = (const float*)d_in[3];  // (32000,)
    float* out = (float*)d_out;                // (4,2048,1024)

    // fork: cvt_e + zero_H on side stream, concurrent with cvt_w/cvt_x/passA
    cudaEventRecord(g_aux.evFork, 0);
    cudaStreamWaitEvent(g_aux.s1, g_aux.evFork, 0);
    cvt_e<<<(V_TOT * (D_DIM / 4)) / 256, 256, 0, g_aux.s1>>>((const float4*)emb);
    zero_H<<<(R_TOT * D_DIM / 4) / 256, 256, 0, g_aux.s1>>>();
    cudaEventRecord(g_aux.evJoin, g_aux.s1);

    cvt_w<<<dim3(V_TOT / 32, F_DIM / 32), dim3(32, 8)>>>(W);
    cvt_x<<<256, 256>>>(x);

    cudaFuncSetAttribute(passA, cudaFuncAttributeMaxDynamicSharedMemorySize, A_SMEM_BYTES);
    passA<<<dim3(V_TOT / AV, R_TOT / AM), 256, A_SMEM_BYTES>>>(b);

    // join: passB needs g_E16 + zeroed g_H
    cudaStreamWaitEvent(0, g_aux.evJoin, 0);
    cudaFuncSetAttribute(passB, cudaFuncAttributeMaxDynamicSharedMemorySize, B_SMEM_BYTES);
    passB<<<NPERS, 256, B_SMEM_BYTES>>>();

    scaleH<<<(R_TOT * D_DIM / 4) / 256, 256>>>((float4*)out);
}